// round 4
// baseline (speedup 1.0000x reference)
#include <cuda_runtime.h>
#include <math.h>

#define QT 16
#define KT 256
#define TT 2048
#define DD 64
#define HH 16
#define BB 2
#define VST 68

// per-row softmax stats scratch (device globals are the allowed scratch path)
__device__ float g_m[BB*HH*TT];
__device__ float g_inv[BB*HH*TT];

__device__ __forceinline__ void ffma2(unsigned long long& d,
                                      unsigned long long a, unsigned long long b) {
    asm("fma.rn.f32x2 %0, %1, %2, %0;" : "+l"(d) : "l"(a), "l"(b));
}
__device__ __forceinline__ unsigned long long dup2(float x) {
    unsigned long long r;
    asm("mov.b64 %0, {%1, %1};" : "=l"(r) : "f"(x));
    return r;
}
__device__ __forceinline__ float2 unpk(unsigned long long v) {
    float2 f;
    asm("mov.b64 {%0, %1}, %2;" : "=f"(f.x), "=f"(f.y) : "l"(v));
    return f;
}

// ============== Kernel A: raw scores -> gattn, online (m, sum) -> g_m/g_inv ==============
// smem floats: K^T 64*256 = 16384 | Q 16*64 = 1024 | red 64  => 69,888 B -> 3 CTAs/SM
#define SMEM_A_FLOATS (DD*KT + QT*DD + 64)

__global__ __launch_bounds__(256, 3)
void qk_softmax_kernel(const float* __restrict__ gq, const float* __restrict__ gk,
                       const int* __restrict__ gmask, const float* __restrict__ gbias,
                       float* __restrict__ gattn)
{
    extern __shared__ float sm[];
    float* s_k   = sm;                 // [64][KT] transposed
    float* s_q   = sm + DD*KT;         // [QT][DD]
    float* s_red = s_q + QT*DD;        // [8 warps][4 rows][2]

    const int t  = threadIdx.x;
    const int h  = blockIdx.y, b = blockIdx.z;
    const int q0 = blockIdx.x * QT;

    const float* qbase    = gq + (((size_t)(b*HH + h))*TT + q0) * DD;
    const float* kbase    = gk + ((size_t)(b*HH + h)) * TT * DD;
    const float* biasbase = gbias + ((size_t)h * TT + q0) * TT;
    const int*   maskb    = gmask + b * TT;
    float*       attnbase = gattn + (((size_t)(b*HH + h))*TT + q0) * TT;

    ((float4*)s_q)[t] = ((const float4*)qbase)[t];

    const int kg = t & 63;      // 4 consecutive k
    const int qg = t >> 6;      // rows {qg+4i}; uniform within warp

    float mr[4], sr[4];
    #pragma unroll
    for (int i = 0; i < 4; ++i) { mr[i] = -3.4e38f; sr[i] = 0.f; }

    for (int kt_ = 0; kt_ < TT/KT; ++kt_) {
        __syncthreads();
        {   // K tile transposed: thread t owns k-row; STS bank = t%32, conflict-free
            const float* krow = kbase + (size_t)(kt_*KT + t) * DD;
            #pragma unroll
            for (int m = 0; m < 16; ++m) {
                float4 f = ((const float4*)krow)[m];
                s_k[(m*4+0)*KT + t] = f.x;
                s_k[(m*4+1)*KT + t] = f.y;
                s_k[(m*4+2)*KT + t] = f.z;
                s_k[(m*4+3)*KT + t] = f.w;
            }
        }
        const int kglob = kt_*KT + kg*4;
        const int4 mv = *(const int4*)&maskb[kglob];
        float4 bi[4];
        #pragma unroll
        for (int i = 0; i < 4; ++i)
            bi[i] = *(const float4*)&biasbase[(size_t)(qg + 4*i)*TT + kglob];
        __syncthreads();

        unsigned long long acc[4][2];
        #pragma unroll
        for (int i = 0; i < 4; ++i) { acc[i][0] = 0ull; acc[i][1] = 0ull; }

        #pragma unroll
        for (int db = 0; db < 16; ++db) {       // 4 d per step; Q refreshed per step
            float qf[4][4];
            #pragma unroll
            for (int i = 0; i < 4; ++i) {
                float4 f = *(const float4*)&s_q[(qg + 4*i)*DD + db*4];
                qf[i][0] = f.x; qf[i][1] = f.y; qf[i][2] = f.z; qf[i][3] = f.w;
            }
            #pragma unroll
            for (int dd = 0; dd < 4; ++dd) {
                ulonglong2 kk = *(const ulonglong2*)&s_k[(db*4 + dd)*KT + kg*4];
                #pragma unroll
                for (int i = 0; i < 4; ++i) {
                    unsigned long long qq = dup2(qf[i][dd]);
                    ffma2(acc[i][0], qq, kk.x);
                    ffma2(acc[i][1], qq, kk.y);
                }
            }
        }

        // epilogue: scale+bias+mask -> raw scores to gmem; online (m,s)
        #pragma unroll
        for (int i = 0; i < 4; ++i) {
            float2 a01 = unpk(acc[i][0]);
            float2 a23 = unpk(acc[i][1]);
            float4 r;
            r.x = (mv.x == 0) ? -1e9f : fmaf(a01.x, 0.125f, bi[i].x);
            r.y = (mv.y == 0) ? -1e9f : fmaf(a01.y, 0.125f, bi[i].y);
            r.z = (mv.z == 0) ? -1e9f : fmaf(a23.x, 0.125f, bi[i].z);
            r.w = (mv.w == 0) ? -1e9f : fmaf(a23.y, 0.125f, bi[i].w);
            *(float4*)&attnbase[(size_t)(qg + 4*i)*TT + kglob] = r;

            float tmax = fmaxf(fmaxf(r.x, r.y), fmaxf(r.z, r.w));
            float mn = fmaxf(mr[i], tmax);
            float c  = __expf(mr[i] - mn);
            sr[i] = sr[i]*c + (__expf(r.x - mn) + __expf(r.y - mn))
                            + (__expf(r.z - mn) + __expf(r.w - mn));
            mr[i] = mn;
        }
    }

    // reduce (m,s) across 32 lanes (all lanes in a warp share the same 4 rows)
    const int lane = t & 31, w = t >> 5;
    #pragma unroll
    for (int i = 0; i < 4; ++i) {
        #pragma unroll
        for (int o = 16; o > 0; o >>= 1) {
            float mo = __shfl_xor_sync(0xffffffffu, mr[i], o);
            float so = __shfl_xor_sync(0xffffffffu, sr[i], o);
            float mn = fmaxf(mr[i], mo);
            sr[i] = sr[i]*__expf(mr[i]-mn) + so*__expf(mo-mn);
            mr[i] = mn;
        }
        if (lane == 0) { s_red[w*8 + i*2] = mr[i]; s_red[w*8 + i*2 + 1] = sr[i]; }
    }
    __syncthreads();
    if (t < 16) {   // combine the 2 warps per qg group
        const int qgr = t & 3, i = t >> 2;
        float m0 = s_red[(2*qgr  )*8 + i*2], s0 = s_red[(2*qgr  )*8 + i*2 + 1];
        float m1 = s_red[(2*qgr+1)*8 + i*2], s1 = s_red[(2*qgr+1)*8 + i*2 + 1];
        float mn = fmaxf(m0, m1);
        float s  = s0*__expf(m0-mn) + s1*__expf(m1-mn);
        size_t gi = (size_t)(b*HH + h)*TT + q0 + qgr + 4*i;
        g_m[gi] = mn; g_inv[gi] = 1.f / s;
    }
}

// ============== Kernel B: normalize attn in-place + out = attn @ V ==============
// smem floats: V 256*68 = 17408 => 69,632 B -> 3 CTAs/SM
#define SMEM_B_FLOATS (KT*VST)

__global__ __launch_bounds__(256, 3)
void pv_kernel(const float* __restrict__ gv, float* __restrict__ gattn,
               float* __restrict__ gout)
{
    extern __shared__ float sm[];
    float* s_v = sm;   // [KT][VST]; reused for output reduction at the end

    const int t  = threadIdx.x;
    const int h  = blockIdx.y, b = blockIdx.z;
    const int q0 = blockIdx.x * QT;

    const float* vbase    = gv + ((size_t)(b*HH + h)) * TT * DD;
    float*       attnbase = gattn + (((size_t)(b*HH + h))*TT + q0) * TT;

    // normalize mapping: rows qgN + 4i, cols (t&63)*4
    const int qgN = t >> 6;
    float m4[4], inv4[4];
    {
        const size_t statb = (size_t)(b*HH + h)*TT + q0;
        #pragma unroll
        for (int i = 0; i < 4; ++i) {
            m4[i]   = g_m[statb + qgN + 4*i];
            inv4[i] = g_inv[statb + qgN + 4*i];
        }
    }

    // PV mapping: 4 rows (4*qg2+i) x 8 d (dg*8..), warp k-split kh
    const int dg  = t & 7;
    const int qg2 = (t >> 3) & 3;
    const int kh  = t >> 5;

    unsigned long long oacc[4][4];
    #pragma unroll
    for (int i = 0; i < 4; ++i)
        #pragma unroll
        for (int j = 0; j < 4; ++j) oacc[i][j] = 0ull;

    const int colbase = (t & 63) * 4;

    for (int kt_ = 0; kt_ < TT/KT; ++kt_) {
        __syncthreads();
        {   // V tile
            const float* vrow = vbase + (size_t)(kt_*KT + t) * DD;
            #pragma unroll
            for (int m = 0; m < 16; ++m)
                *(float4*)&s_v[t*VST + m*4] = ((const float4*)vrow)[m];
        }
        // normalize this score tile in-place (overlaps V-store latency)
        #pragma unroll
        for (int i = 0; i < 4; ++i) {
            float* p = attnbase + (size_t)(qgN + 4*i)*TT + kt_*KT + colbase;
            float4 x = *(const float4*)p;
            x.x = __expf(x.x - m4[i]) * inv4[i];
            x.y = __expf(x.y - m4[i]) * inv4[i];
            x.z = __expf(x.z - m4[i]) * inv4[i];
            x.w = __expf(x.w - m4[i]) * inv4[i];
            *(float4*)p = x;
        }
        __syncthreads();   // V in smem + normalized p visible block-wide

        #pragma unroll 2
        for (int kc = 0; kc < 8; ++kc) {
            const int k0 = kh*32 + kc*4;
            float a[4][4];
            #pragma unroll
            for (int i = 0; i < 4; ++i) {
                float4 a4 = *(const float4*)&attnbase[(size_t)(4*qg2 + i)*TT + kt_*KT + k0];
                a[i][0] = a4.x; a[i][1] = a4.y; a[i][2] = a4.z; a[i][3] = a4.w;
            }
            #pragma unroll
            for (int kk = 0; kk < 4; ++kk) {
                ulonglong2 v0 = *(const ulonglong2*)&s_v[(k0 + kk)*VST + dg*8];
                ulonglong2 v1 = *(const ulonglong2*)&s_v[(k0 + kk)*VST + dg*8 + 4];
                #pragma unroll
                for (int i = 0; i < 4; ++i) {
                    unsigned long long aa = dup2(a[i][kk]);
                    ffma2(oacc[i][0], aa, v0.x);
                    ffma2(oacc[i][1], aa, v0.y);
                    ffma2(oacc[i][2], aa, v1.x);
                    ffma2(oacc[i][3], aa, v1.y);
                }
            }
        }
    }

    // reduce 8 warp k-split partials via smem (s_v is free now)
    __syncthreads();
    #pragma unroll
    for (int i = 0; i < 4; ++i) {
        float2 p0 = unpk(oacc[i][0]);
        float2 p1 = unpk(oacc[i][1]);
        float2 p2 = unpk(oacc[i][2]);
        float2 p3 = unpk(oacc[i][3]);
        float* dst = &s_v[kh*1024 + (4*qg2 + i)*64 + dg*8];
        *(float4*)&dst[0] = make_float4(p0.x, p0.y, p1.x, p1.y);
        *(float4*)&dst[4] = make_float4(p2.x, p2.y, p3.x, p3.y);
    }
    __syncthreads();
    {
        const int o = t * 4;
        float4 s = *(const float4*)&s_v[o];
        #pragma unroll
        for (int p = 1; p < 8; ++p) {
            float4 x = *(const float4*)&s_v[p*1024 + o];
            s.x += x.x; s.y += x.y; s.z += x.z; s.w += x.w;
        }
        float* obase = gout + (((size_t)(b*HH + h))*TT + q0) * DD;
        *(float4*)&obase[o] = s;
    }
}

extern "C" void kernel_launch(void* const* d_in, const int* in_sizes, int n_in,
                              void* d_out, int out_size)
{
    const float* q    = (const float*)d_in[0];
    const float* k    = (const float*)d_in[1];
    const float* v    = (const float*)d_in[2];
    const int*   mask = (const int*)d_in[3];
    const float* bias = (const float*)d_in[4];
    float* out  = (float*)d_out;
    float* attn = out + (long long)BB*HH*TT*DD;   // second output region

    cudaFuncSetAttribute(qk_softmax_kernel,
        cudaFuncAttributeMaxDynamicSharedMemorySize, (int)(SMEM_A_FLOATS*sizeof(float)));
    cudaFuncSetAttribute(pv_kernel,
        cudaFuncAttributeMaxDynamicSharedMemorySize, (int)(SMEM_B_FLOATS*sizeof(float)));

    dim3 grid(TT/QT, HH, BB);
    qk_softmax_kernel<<<grid, 256, SMEM_A_FLOATS*sizeof(float)>>>(q, k, mask, bias, attn);
    pv_kernel<<<grid, 256, SMEM_B_FLOATS*sizeof(float)>>>(v, attn, out);
}

// round 6
// speedup vs baseline: 1.5979x; 1.5979x over previous
#include <cuda_runtime.h>
#include <math.h>

#define TT 2048
#define DD 64
#define HH 16
#define BB 2

#define QTA 32          // q-tile kernel A
#define KTA 256         // k-tile kernel A
#define QTB 32          // q-tile kernel B
#define KTB 128         // k-tile kernel B
#define VST 68          // V smem row stride (MULTIPLE OF 4 for float4 alignment)
#define PST 132         // p smem row stride (multiple of 4)

__device__ float g_m[BB*HH*TT];
__device__ float g_inv[BB*HH*TT];

__device__ __forceinline__ void ffma2(unsigned long long& d,
                                      unsigned long long a, unsigned long long b) {
    asm("fma.rn.f32x2 %0, %1, %2, %0;" : "+l"(d) : "l"(a), "l"(b));
}
__device__ __forceinline__ unsigned long long dup2(float x) {
    unsigned long long r;
    asm("mov.b64 %0, {%1, %1};" : "=l"(r) : "f"(x));
    return r;
}
__device__ __forceinline__ float2 unpk(unsigned long long v) {
    float2 f;
    asm("mov.b64 {%0, %1}, %2;" : "=f"(f.x), "=f"(f.y) : "l"(v));
    return f;
}

// ===================== Kernel A: QK^T -> raw scores + online (m, 1/sum) =====================
// smem: K^T [64][256] = 16384 fl | Q [32][64] = 2048 fl (reused as s_red)  => 73,728 B
#define SMEM_A_FLOATS (DD*KTA + QTA*DD)

__global__ __launch_bounds__(256, 2)
void qk_kernel(const float* __restrict__ gq, const float* __restrict__ gk,
               const int* __restrict__ gmask, const float* __restrict__ gbias,
               float* __restrict__ gattn)
{
    extern __shared__ float sm[];
    float* s_k = sm;               // [64][KTA] transposed
    float* s_q = sm + DD*KTA;      // [QTA][DD]; overlaid by s_red after compute

    const int t  = threadIdx.x;
    const int h  = blockIdx.y, b = blockIdx.z;
    const int q0 = blockIdx.x * QTA;

    const float* qbase    = gq + (((size_t)(b*HH + h))*TT + q0) * DD;
    const float* kbase    = gk + ((size_t)(b*HH + h)) * TT * DD;
    const float* biasbase = gbias + ((size_t)h * TT + q0) * TT;
    const int*   maskb    = gmask + b * TT;
    float*       attnbase = gattn + (((size_t)(b*HH + h))*TT + q0) * TT;

    // Q tile: 2048 floats = 512 float4, 2 per thread
    ((float4*)s_q)[t]       = ((const float4*)qbase)[t];
    ((float4*)s_q)[t + 256] = ((const float4*)qbase)[t + 256];

    const int kg = t & 63;     // 4 consecutive k cols: kg*4
    const int qg = t >> 6;     // rows {qg + 4i, i=0..7}; warp-uniform

    float mr[8], sr[8];
    #pragma unroll
    for (int i = 0; i < 8; ++i) { mr[i] = -3.4e38f; sr[i] = 0.f; }

    for (int kt = 0; kt < TT/KTA; ++kt) {
        __syncthreads();
        {   // stage K transposed: thread t owns k-row; STS bank = t%32, conflict-free
            const float* krow = kbase + (size_t)(kt*KTA + t) * DD;
            #pragma unroll
            for (int m = 0; m < 16; ++m) {
                float4 f = ((const float4*)krow)[m];
                s_k[(m*4+0)*KTA + t] = f.x;
                s_k[(m*4+1)*KTA + t] = f.y;
                s_k[(m*4+2)*KTA + t] = f.z;
                s_k[(m*4+3)*KTA + t] = f.w;
            }
        }
        __syncthreads();

        unsigned long long acc[8][2];
        #pragma unroll
        for (int i = 0; i < 8; ++i) { acc[i][0] = 0ull; acc[i][1] = 0ull; }

        #pragma unroll
        for (int db = 0; db < 16; ++db) {
            float4 qv[8];
            #pragma unroll
            for (int i = 0; i < 8; ++i)
                qv[i] = *(const float4*)&s_q[(qg + 4*i)*DD + db*4];   // warp bcast

            {   ulonglong2 kk = *(const ulonglong2*)&s_k[(db*4+0)*KTA + kg*4];
                #pragma unroll
                for (int i = 0; i < 8; ++i) {
                    unsigned long long qq = dup2(qv[i].x);
                    ffma2(acc[i][0], qq, kk.x); ffma2(acc[i][1], qq, kk.y);
                } }
            {   ulonglong2 kk = *(const ulonglong2*)&s_k[(db*4+1)*KTA + kg*4];
                #pragma unroll
                for (int i = 0; i < 8; ++i) {
                    unsigned long long qq = dup2(qv[i].y);
                    ffma2(acc[i][0], qq, kk.x); ffma2(acc[i][1], qq, kk.y);
                } }
            {   ulonglong2 kk = *(const ulonglong2*)&s_k[(db*4+2)*KTA + kg*4];
                #pragma unroll
                for (int i = 0; i < 8; ++i) {
                    unsigned long long qq = dup2(qv[i].z);
                    ffma2(acc[i][0], qq, kk.x); ffma2(acc[i][1], qq, kk.y);
                } }
            {   ulonglong2 kk = *(const ulonglong2*)&s_k[(db*4+3)*KTA + kg*4];
                #pragma unroll
                for (int i = 0; i < 8; ++i) {
                    unsigned long long qq = dup2(qv[i].w);
                    ffma2(acc[i][0], qq, kk.x); ffma2(acc[i][1], qq, kk.y);
                } }
        }

        // epilogue: scale + bias + mask -> raw scores to gmem; online (m,s)
        const int kglob = kt*KTA + kg*4;
        const int4 mv = *(const int4*)&maskb[kglob];
        #pragma unroll
        for (int i = 0; i < 8; ++i) {
            const int r_ = qg + 4*i;
            float4 bi = *(const float4*)&biasbase[(size_t)r_*TT + kglob];
            float2 a01 = unpk(acc[i][0]);
            float2 a23 = unpk(acc[i][1]);
            float4 r;
            r.x = (mv.x == 0) ? -1e9f : fmaf(a01.x, 0.125f, bi.x);
            r.y = (mv.y == 0) ? -1e9f : fmaf(a01.y, 0.125f, bi.y);
            r.z = (mv.z == 0) ? -1e9f : fmaf(a23.x, 0.125f, bi.z);
            r.w = (mv.w == 0) ? -1e9f : fmaf(a23.y, 0.125f, bi.w);
            *(float4*)&attnbase[(size_t)r_*TT + kglob] = r;

            float tmax = fmaxf(fmaxf(r.x, r.y), fmaxf(r.z, r.w));
            float mn = fmaxf(mr[i], tmax);
            sr[i] = sr[i]*__expf(mr[i] - mn)
                  + (__expf(r.x - mn) + __expf(r.y - mn))
                  + (__expf(r.z - mn) + __expf(r.w - mn));
            mr[i] = mn;
        }
    }

    __syncthreads();              // everyone done reading s_q before overlay
    float* s_red = s_q;           // [8 warps][8 rows][2]
    const int lane = t & 31, w = t >> 5;
    #pragma unroll
    for (int i = 0; i < 8; ++i) {
        #pragma unroll
        for (int o = 16; o > 0; o >>= 1) {
            float mo = __shfl_xor_sync(0xffffffffu, mr[i], o);
            float so = __shfl_xor_sync(0xffffffffu, sr[i], o);
            float mn = fmaxf(mr[i], mo);
            sr[i] = sr[i]*__expf(mr[i]-mn) + so*__expf(mo-mn);
            mr[i] = mn;
        }
        if (lane == 0) { s_red[w*16 + i*2] = mr[i]; s_red[w*16 + i*2 + 1] = sr[i]; }
    }
    __syncthreads();
    if (t < 32) {                 // row = t; owned by warps 2*(row&3), +1 at slot i=row>>2
        const int qg_ = t & 3, i = t >> 2;
        const int w0 = 2*qg_, w1 = 2*qg_ + 1;
        float m0 = s_red[w0*16 + i*2], s0 = s_red[w0*16 + i*2 + 1];
        float m1 = s_red[w1*16 + i*2], s1 = s_red[w1*16 + i*2 + 1];
        float mn = fmaxf(m0, m1);
        float s  = s0*__expf(m0 - mn) + s1*__expf(m1 - mn);
        size_t gi = (size_t)(b*HH + h)*TT + q0 + t;
        g_m[gi] = mn; g_inv[gi] = 1.f / s;
    }
}

// ===================== Kernel B: normalize attn (via smem) + out = attn @ V =====================
// smem: V [128][68] = 8704 fl | p [32][132] = 4224 fl  => 51,712 B -> 3 CTAs/SM
#define SMEM_B_FLOATS (KTB*VST + QTB*PST)

__global__ __launch_bounds__(256, 3)
void pv_kernel(const float* __restrict__ gv, float* __restrict__ gattn,
               float* __restrict__ gout)
{
    extern __shared__ float sm[];
    float* s_v = sm;               // [KTB][VST]; reused for partial reduction
    float* s_p = sm + KTB*VST;     // [QTB][PST]

    const int t  = threadIdx.x;
    const int h  = blockIdx.y, b = blockIdx.z;
    const int q0 = blockIdx.x * QTB;

    const float* vbase    = gv + ((size_t)(b*HH + h)) * TT * DD;
    float*       attnbase = gattn + (((size_t)(b*HH + h))*TT + q0) * TT;
    const size_t statb    = (size_t)(b*HH + h)*TT + q0;

    // normalize mapping: row nr = t>>3, cols (t&7)*16 .. +15
    const int nr = t >> 3, c0 = (t & 7) * 16;
    const float nm   = g_m[statb + nr];
    const float ninv = g_inv[statb + nr];

    // PV mapping: d = dg*4, rows {qg2+4i}, k-split kh (warp-pair uniform)
    const int dg  = t & 15;
    const int qg2 = (t >> 4) & 3;
    const int kh  = t >> 6;

    unsigned long long oacc[8][2];
    #pragma unroll
    for (int i = 0; i < 8; ++i) { oacc[i][0] = 0ull; oacc[i][1] = 0ull; }

    for (int kt = 0; kt < TT/KTB; ++kt) {
        __syncthreads();
        {   // stage V: thread t owns half-row (row t>>1, half t&1)
            const float* vrow = vbase + (size_t)(kt*KTB + (t>>1))*DD + (t&1)*32;
            float* srow = &s_v[(t>>1)*VST + (t&1)*32];
            #pragma unroll
            for (int m = 0; m < 8; ++m)
                *(float4*)&srow[m*4] = ((const float4*)vrow)[m];
        }
        {   // normalize raw scores -> gmem attn + smem p
            float* graw = attnbase + (size_t)nr*TT + kt*KTB + c0;
            float* prow = &s_p[nr*PST + c0];
            #pragma unroll
            for (int j = 0; j < 4; ++j) {
                float4 x = *(const float4*)&graw[j*4];
                x.x = __expf(x.x - nm) * ninv;
                x.y = __expf(x.y - nm) * ninv;
                x.z = __expf(x.z - nm) * ninv;
                x.w = __expf(x.w - nm) * ninv;
                *(float4*)&graw[j*4] = x;
                *(float4*)&prow[j*4] = x;
            }
        }
        __syncthreads();

        #pragma unroll
        for (int kc = 0; kc < 8; ++kc) {
            const int k0 = kh*32 + kc*4;
            float4 pr[8];
            #pragma unroll
            for (int i = 0; i < 8; ++i)
                pr[i] = *(const float4*)&s_p[(qg2 + 4*i)*PST + k0];   // bcast

            #pragma unroll
            for (int kk = 0; kk < 4; ++kk) {
                ulonglong2 vv = *(const ulonglong2*)&s_v[(k0 + kk)*VST + dg*4];
                #pragma unroll
                for (int i = 0; i < 8; ++i) {
                    float pv = (kk == 0) ? pr[i].x : (kk == 1) ? pr[i].y
                             : (kk == 2) ? pr[i].z : pr[i].w;
                    unsigned long long aa = dup2(pv);
                    ffma2(oacc[i][0], aa, vv.x);
                    ffma2(oacc[i][1], aa, vv.y);
                }
            }
        }
    }

    // reduce 4 k-split partials via smem (s_v free now)
    __syncthreads();
    #pragma unroll
    for (int i = 0; i < 8; ++i) {
        float2 p0 = unpk(oacc[i][0]);
        float2 p1 = unpk(oacc[i][1]);
        *(float4*)&s_v[kh*2048 + (qg2 + 4*i)*64 + dg*4] =
            make_float4(p0.x, p0.y, p1.x, p1.y);
    }
    __syncthreads();
    {
        const int o = t * 8;      // 2048 outputs, 8 per thread
        float4 s0 = *(const float4*)&s_v[o];
        float4 s1 = *(const float4*)&s_v[o + 4];
        #pragma unroll
        for (int p = 1; p < 4; ++p) {
            float4 x0 = *(const float4*)&s_v[p*2048 + o];
            float4 x1 = *(const float4*)&s_v[p*2048 + o + 4];
            s0.x += x0.x; s0.y += x0.y; s0.z += x0.z; s0.w += x0.w;
            s1.x += x1.x; s1.y += x1.y; s1.z += x1.z; s1.w += x1.w;
        }
        float* obase = gout + (((size_t)(b*HH + h))*TT + q0) * DD;
        *(float4*)&obase[o]     = s0;
        *(float4*)&obase[o + 4] = s1;
    }
}

extern "C" void kernel_launch(void* const* d_in, const int* in_sizes, int n_in,
                              void* d_out, int out_size)
{
    const float* q    = (const float*)d_in[0];
    const float* k    = (const float*)d_in[1];
    const float* v    = (const float*)d_in[2];
    const int*   mask = (const int*)d_in[3];
    const float* bias = (const float*)d_in[4];
    float* out  = (float*)d_out;
    float* attn = out + (long long)BB*HH*TT*DD;

    cudaFuncSetAttribute(qk_kernel,
        cudaFuncAttributeMaxDynamicSharedMemorySize, (int)(SMEM_A_FLOATS*sizeof(float)));
    cudaFuncSetAttribute(pv_kernel,
        cudaFuncAttributeMaxDynamicSharedMemorySize, (int)(SMEM_B_FLOATS*sizeof(float)));

    dim3 gridA(TT/QTA, HH, BB);
    dim3 gridB(TT/QTB, HH, BB);
    qk_kernel<<<gridA, 256, SMEM_A_FLOATS*sizeof(float)>>>(q, k, mask, bias, attn);
    pv_kernel<<<gridB, 256, SMEM_B_FLOATS*sizeof(float)>>>(v, attn, out);
}